// round 13
// baseline (speedup 1.0000x reference)
#include <cuda_runtime.h>
#include <cuda_bf16.h>

// Problem constants
#define TOKENS   65536          // 16*64*64
#define DDIM     256
#define KCODES   1024
#define Z_ELEMS  (TOKENS * DDIM)   // 16777216
#define BETA     0.25f
#define EPS_F    1e-5f

// Certified window on s = e2 - 2*ze: E = bf16 mma error <= 2.4e-3; W > 2E.
// Selection thresholds use the RUNNING min (>= final min), so the selected
// set is a superset of the certified window — no candidate can be missed.
#define W_WINDOW 0.01f
#define CAND_CAP 16

#define NBLK_MMA  (TOKENS / 64)        // 1024  (64 tokens per CTA)
#define NBLK_RR   (TOKENS / 8)         // 8192  (8 tokens per CTA)

// Phase-1 smem: z bf16 [64][264] | cb stages 2x[256][40] bf16 | e2[1024]
//              | smin[64] scnt[64] scand[64][16]
#define P1_ZB_ELEMS   (64 * 264)                   // 16896 bf16
#define P1_CB_ELEMS   (256 * 40)                   // per stage
#define P1_SMEM_BYTES (P1_ZB_ELEMS * 2 + 2 * P1_CB_ELEMS * 2 + 1024 * 4 \
                       + (64 + 64 + 64 * CAND_CAP) * 4)          // 83456

// Output layout: [0..Z) z_q_st | [Z+0..3] scalars | [Z+4..) indices as float

// Device scratch (static: no allocations allowed)
__device__ int            g_counts[KCODES];
__device__ double         g_partial[NBLK_RR];
__device__ float          g_e2[KCODES];
__device__ float          g_z2[TOKENS];
__device__ __nv_bfloat16  g_cb_bf16[KCODES * DDIM];
__device__ __nv_bfloat16  g_z_bf16[TOKENS * DDIM];
__device__ int            g_ccnt[TOKENS];
__device__ int            g_cand[(size_t)TOKENS * CAND_CAP];

// order-preserving float <-> uint key (ascending)
__device__ __forceinline__ unsigned okey(float v) {
    unsigned b = __float_as_uint(v);
    return b ^ (unsigned)(((int)b >> 31) | 0x80000000);
}
__device__ __forceinline__ float odec(unsigned k) {
    unsigned b = (k & 0x80000000u) ? (k ^ 0x80000000u) : ~k;
    return __uint_as_float(b);
}

// ---------------------------------------------------------------------------
// prep codebook: exact e2 (reference order) + bf16 copy + zero histogram.
// ---------------------------------------------------------------------------
__global__ void __launch_bounds__(256) vq_prep_cb(const float* __restrict__ cb) {
    __shared__ float ct[32 * 260];
    const int tid = threadIdx.x;
    const int k0  = blockIdx.x * 32;
    if (blockIdx.x < 4) g_counts[blockIdx.x * 256 + tid] = 0;
    const float* cbb = cb + (size_t)k0 * DDIM;
    #pragma unroll
    for (int p = 0; p < 32; p++) {
        int e = tid + p * 256;            // 0..8191
        float v = cbb[e];
        ct[(e >> 8) * 260 + (e & 255)] = v;
        g_cb_bf16[(size_t)k0 * DDIM + e] = __float2bfloat16_rn(v);
    }
    __syncthreads();
    if (tid < 32) {
        const float* row = &ct[tid * 260];
        float s = 0.0f;
        #pragma unroll 8
        for (int d = 0; d < DDIM; d++)
            s = __fadd_rn(s, __fmul_rn(row[d], row[d]));
        g_e2[k0 + tid] = s;
    }
}

// ---------------------------------------------------------------------------
// prep z: exact z2 (reference order via padded transpose) + bf16 copy.
// ---------------------------------------------------------------------------
__global__ void __launch_bounds__(256) vq_prep_z(const float* __restrict__ z) {
    __shared__ float zt[32 * 257];
    const int tid  = threadIdx.x;
    const int tok0 = blockIdx.x * 32;
    const float* zb = z + (size_t)tok0 * DDIM;
    #pragma unroll
    for (int p = 0; p < 32; p++) {
        int e = tid + p * 256;
        float v = zb[e];
        zt[(e >> 8) * 257 + (e & 255)] = v;
        g_z_bf16[(size_t)tok0 * DDIM + e] = __float2bfloat16_rn(v);
    }
    __syncthreads();
    if (tid < 32) {
        const float* row = &zt[tid * 257];
        float s = 0.0f;
        #pragma unroll 8
        for (int d = 0; d < DDIM; d++)
            s = __fadd_rn(s, __fmul_rn(row[d], row[d]));
        g_z2[tok0 + tid] = s;
    }
}

// ---------------------------------------------------------------------------
// Phase 1: bf16 mma + FUSED candidate selection (no s matrix).
// CTA = 64 tokens x 1024 codes. 8 warps: mw = w&3 token rows; nh = w>>2 half.
// Per chunk epilogue: block running min per token (ordered-uint atomicMin),
// then select s <= running_min + W into per-token candidate lists.
// ---------------------------------------------------------------------------
__global__ void __launch_bounds__(256, 2) vq_mma() {
    extern __shared__ char smem[];
    __nv_bfloat16* zbs = reinterpret_cast<__nv_bfloat16*>(smem);       // [64][264]
    __nv_bfloat16* cbs = zbs + P1_ZB_ELEMS;                            // [2][256][40]
    float*    e2s  = reinterpret_cast<float*>(cbs + 2 * P1_CB_ELEMS);  // [1024]
    unsigned* smin = reinterpret_cast<unsigned*>(e2s + 1024);          // [64]
    int*      scnt = reinterpret_cast<int*>(smin + 64);                // [64]
    int*      scand = scnt + 64;                                       // [64][16]

    const int tid  = threadIdx.x;
    const int lane = tid & 31;
    const int w    = tid >> 5;
    const int mw   = w & 3;
    const int nh   = w >> 2;
    const int tok0 = blockIdx.x * 64;
    const int gid  = lane >> 2;     // groupID
    const int tg   = lane & 3;      // thread-in-group

    // Load z bf16 tile: 2048 x 16B, rows padded to 264.
    {
        const uint4* zg = reinterpret_cast<const uint4*>(g_z_bf16 + (size_t)tok0 * DDIM);
        #pragma unroll
        for (int p = 0; p < 8; p++) {
            int idx = tid + p * 256;          // 0..2047
            int r   = idx >> 5;               // 0..63
            int c8  = idx & 31;
            *reinterpret_cast<uint4*>(zbs + r * 264 + c8 * 8) = zg[idx];
        }
    }
    #pragma unroll
    for (int p = 0; p < 4; p++) e2s[tid + p * 256] = g_e2[tid + p * 256];
    if (tid < 64) { smin[tid] = 0xFFFFFFFFu; scnt[tid] = 0; }

    // stage SI (0..31): chunk = SI>>3, d-stage = SI&7 (32 d per stage)
    #define SL(SI, BUF)                                                          \
    do {                                                                         \
        int c_  = (SI) >> 3;                                                     \
        int st_ = (SI) & 7;                                                      \
        _Pragma("unroll")                                                        \
        for (int q = 0; q < 4; q++) {                                            \
            int idx_ = tid + q * 256;          /* 0..1023 */                     \
            int r_   = idx_ >> 2;              /* 0..255  */                     \
            int sg_  = idx_ & 3;                                                 \
            int g_   = c_ * 128 + (r_ & 127) + (r_ >> 7) * 512;                  \
            const __nv_bfloat16* src_ =                                          \
                g_cb_bf16 + (size_t)g_ * DDIM + st_ * 32 + sg_ * 8;              \
            unsigned dst_ = (unsigned)__cvta_generic_to_shared(                  \
                cbs + (BUF) * P1_CB_ELEMS + r_ * 40 + sg_ * 8);                  \
            asm volatile("cp.async.cg.shared.global [%0], [%1], 16;\n"           \
                         :: "r"(dst_), "l"(src_));                               \
        }                                                                        \
        asm volatile("cp.async.commit_group;\n" ::: "memory");                   \
    } while (0)

    SL(0, 0);
    float acc[16][4];
    int buf = 0;

    for (int c = 0; c < 4; c++) {
        #pragma unroll
        for (int nt = 0; nt < 16; nt++)
            #pragma unroll
            for (int e = 0; e < 4; e++) acc[nt][e] = 0.0f;

        for (int st = 0; st < 8; st++) {
            int sg = c * 8 + st;
            asm volatile("cp.async.wait_group 0;\n" ::: "memory");
            __syncthreads();
            if (sg + 1 < 32) SL(sg + 1, buf ^ 1);

            const __nv_bfloat16* zb =
                zbs + (mw * 16 + gid) * 264 + st * 32 + tg * 2;
            const __nv_bfloat16* cbb =
                cbs + buf * P1_CB_ELEMS + (nh * 128 + gid) * 40 + tg * 2;

            #pragma unroll
            for (int k16 = 0; k16 < 2; k16++) {
                unsigned a0 = *reinterpret_cast<const unsigned*>(zb + k16 * 16);
                unsigned a1 = *reinterpret_cast<const unsigned*>(zb + k16 * 16 + 8 * 264);
                unsigned a2 = *reinterpret_cast<const unsigned*>(zb + k16 * 16 + 8);
                unsigned a3 = *reinterpret_cast<const unsigned*>(zb + k16 * 16 + 8 * 264 + 8);
                #pragma unroll
                for (int nt = 0; nt < 16; nt++) {
                    unsigned b0 = *reinterpret_cast<const unsigned*>(
                        cbb + nt * 320 + k16 * 16);
                    unsigned b1 = *reinterpret_cast<const unsigned*>(
                        cbb + nt * 320 + k16 * 16 + 8);
                    asm volatile(
                        "mma.sync.aligned.m16n8k16.row.col.f32.bf16.bf16.f32 "
                        "{%0,%1,%2,%3}, {%4,%5,%6,%7}, {%8,%9}, {%0,%1,%2,%3};"
                        : "+f"(acc[nt][0]), "+f"(acc[nt][1]),
                          "+f"(acc[nt][2]), "+f"(acc[nt][3])
                        : "r"(a0), "r"(a1), "r"(a2), "r"(a3), "r"(b0), "r"(b1));
                }
            }
            buf ^= 1;
        }

        // ---- fused epilogue: running min + candidate selection ----
        const int t0 = mw * 16 + gid;
        const int kb = nh * 512 + c * 128 + tg * 2;
        // pass 1: thread-local min over this chunk's values for both tokens
        float m0 = 3.4e38f, m1 = 3.4e38f;
        #pragma unroll
        for (int nt = 0; nt < 16; nt++) {
            float e20 = e2s[kb + nt * 8], e21 = e2s[kb + nt * 8 + 1];
            m0 = fminf(m0, fminf(e20 - 2.0f * acc[nt][0],
                                 e21 - 2.0f * acc[nt][1]));
            m1 = fminf(m1, fminf(e20 - 2.0f * acc[nt][2],
                                 e21 - 2.0f * acc[nt][3]));
        }
        atomicMin(&smin[t0], okey(m0));
        atomicMin(&smin[t0 + 8], okey(m1));
        __syncthreads();
        // pass 2: select against running thresholds (superset of final window)
        {
            float thr0 = odec(smin[t0]) + W_WINDOW;
            float thr1 = odec(smin[t0 + 8]) + W_WINDOW;
            #pragma unroll
            for (int nt = 0; nt < 16; nt++) {
                int kg = kb + nt * 8;
                float e20 = e2s[kg], e21 = e2s[kg + 1];
                float s00 = e20 - 2.0f * acc[nt][0];
                float s01 = e21 - 2.0f * acc[nt][1];
                float s10 = e20 - 2.0f * acc[nt][2];
                float s11 = e21 - 2.0f * acc[nt][3];
                if (s00 <= thr0) { int p = atomicAdd(&scnt[t0], 1);
                    if (p < CAND_CAP) scand[t0 * CAND_CAP + p] = kg; }
                if (s01 <= thr0) { int p = atomicAdd(&scnt[t0], 1);
                    if (p < CAND_CAP) scand[t0 * CAND_CAP + p] = kg + 1; }
                if (s10 <= thr1) { int p = atomicAdd(&scnt[t0 + 8], 1);
                    if (p < CAND_CAP) scand[(t0 + 8) * CAND_CAP + p] = kg; }
                if (s11 <= thr1) { int p = atomicAdd(&scnt[t0 + 8], 1);
                    if (p < CAND_CAP) scand[(t0 + 8) * CAND_CAP + p] = kg + 1; }
            }
        }
    }
    #undef SL

    // write candidates out
    __syncthreads();
    if (tid < 64) g_ccnt[tok0 + tid] = scnt[tid];
    #pragma unroll
    for (int p = 0; p < 4; p++) {
        int i = tid + p * 256;            // 0..1023
        g_cand[(size_t)(tok0 + (i >> 4)) * CAND_CAP + (i & 15)] = scand[i];
    }
}

// ---------------------------------------------------------------------------
// Phase 2: per token (1 warp): exact re-rank of candidates (warp-cooperative
// split-d dot + shfl butterfly), then fused gather + z_q_st + loss + hist.
// ---------------------------------------------------------------------------
__global__ void __launch_bounds__(256)
vq_rerank(const float* __restrict__ z, const float* __restrict__ cb,
          float* __restrict__ out) {
    __shared__ float  zsr[8 * DDIM];          // 8 token rows fp32
    __shared__ int    sfin[8];
    __shared__ double dred[256];

    const int tid  = threadIdx.x;
    const int lane = tid & 31;
    const int w    = tid >> 5;
    const int tok0 = blockIdx.x * 8;
    const int t    = tok0 + w;

    // stage z rows (512 float4)
    {
        const float4* zg = reinterpret_cast<const float4*>(z) + (size_t)tok0 * (DDIM / 4);
        #pragma unroll
        for (int p = 0; p < 2; p++) {
            int idx = tid + p * 256;
            reinterpret_cast<float4*>(zsr)[idx] = zg[idx];
        }
    }
    __syncthreads();

    const int cnt = g_ccnt[t];
    float bd = 3.4e38f;
    int   bk = 0;
    const float* zr  = zsr + w * DDIM;
    const float  z2t = g_z2[t];
    const float4* zr4 = reinterpret_cast<const float4*>(zr) + lane * 2;
    float4 zv0 = zr4[0], zv1 = zr4[1];

    #define EXACT_STEP(K)                                                        \
    do {                                                                         \
        int k_ = (K);                                                            \
        const float4* er_ = reinterpret_cast<const float4*>(                     \
            cb + (size_t)k_ * DDIM) + lane * 2;                                  \
        float4 e0_ = er_[0], e1_ = er_[1];                                       \
        float s_ = 0.0f;                                                         \
        s_ = __fmaf_rn(zv0.x, e0_.x, s_);                                        \
        s_ = __fmaf_rn(zv0.y, e0_.y, s_);                                        \
        s_ = __fmaf_rn(zv0.z, e0_.z, s_);                                        \
        s_ = __fmaf_rn(zv0.w, e0_.w, s_);                                        \
        s_ = __fmaf_rn(zv1.x, e1_.x, s_);                                        \
        s_ = __fmaf_rn(zv1.y, e1_.y, s_);                                        \
        s_ = __fmaf_rn(zv1.z, e1_.z, s_);                                        \
        s_ = __fmaf_rn(zv1.w, e1_.w, s_);                                        \
        _Pragma("unroll")                                                        \
        for (int off_ = 16; off_ > 0; off_ >>= 1)                                \
            s_ = __fadd_rn(s_, __shfl_xor_sync(0xFFFFFFFFu, s_, off_));          \
        float dist_ = __fsub_rn(__fadd_rn(z2t, g_e2[k_]),                        \
                                __fmul_rn(2.0f, s_));                            \
        if (dist_ < bd || (dist_ == bd && k_ < bk)) { bd = dist_; bk = k_; }     \
    } while (0)

    if (cnt <= CAND_CAP) {
        const int* cp = &g_cand[(size_t)t * CAND_CAP];
        for (int cc = 0; cc < cnt; cc++) EXACT_STEP(cp[cc]);
    } else {
        for (int k = 0; k < KCODES; k++) EXACT_STEP(k);   // certified fallback
    }
    #undef EXACT_STEP

    if (lane == 0) {
        sfin[w] = bk;
        out[Z_ELEMS + 4 + t] = (float)bk;
        atomicAdd(&g_counts[bk], 1);
    }
    __syncthreads();

    // fused gather + z_q_st + loss partial
    double sacc = 0.0;
    const float4* cb4 = reinterpret_cast<const float4*>(cb);
    float4*       o4  = reinterpret_cast<float4*>(out);
    #pragma unroll
    for (int p = 0; p < 2; p++) {
        int e4 = tid + p * 256;           // 0..511
        int tl = e4 >> 6;
        int d4 = e4 & 63;
        int idx = sfin[tl];
        float4 zq = cb4[(size_t)idx * (DDIM / 4) + d4];
        float4 zz = reinterpret_cast<const float4*>(zsr)[e4];
        float4 o;
        o.x = __fadd_rn(zz.x, __fsub_rn(zq.x, zz.x));
        o.y = __fadd_rn(zz.y, __fsub_rn(zq.y, zz.y));
        o.z = __fadd_rn(zz.z, __fsub_rn(zq.z, zz.z));
        o.w = __fadd_rn(zz.w, __fsub_rn(zq.w, zz.w));
        o4[(size_t)tok0 * (DDIM / 4) + e4] = o;
        float dx = __fsub_rn(zz.x, zq.x);
        float dy = __fsub_rn(zz.y, zq.y);
        float dz = __fsub_rn(zz.z, zq.z);
        float dw = __fsub_rn(zz.w, zq.w);
        sacc += (double)__fmul_rn(dx, dx);
        sacc += (double)__fmul_rn(dy, dy);
        sacc += (double)__fmul_rn(dz, dz);
        sacc += (double)__fmul_rn(dw, dw);
    }
    dred[tid] = sacc;
    __syncthreads();
    for (int stride = 128; stride > 0; stride >>= 1) {
        if (tid < stride) dred[tid] += dred[tid + stride];
        __syncthreads();
    }
    if (tid == 0) g_partial[blockIdx.x] = dred[0];
}

// ---------------------------------------------------------------------------
// finalize (parallel, deterministic fixed-tree reductions in double).
// ---------------------------------------------------------------------------
__global__ void __launch_bounds__(256) vq_finalize(float* __restrict__ out) {
    __shared__ double dr[256];
    __shared__ double hr[256];
    __shared__ int    cr[256];
    const int tid = threadIdx.x;

    double s = 0.0;
    for (int q = 0; q < NBLK_RR / 256; q++) s += g_partial[tid * (NBLK_RR / 256) + q];
    dr[tid] = s;

    int c = 0;
    #pragma unroll
    for (int q = 0; q < 4; q++) c += g_counts[tid * 4 + q];
    cr[tid] = c;
    __syncthreads();
    for (int st = 128; st > 0; st >>= 1) {
        if (tid < st) { dr[tid] += dr[tid + st]; cr[tid] += cr[tid + st]; }
        __syncthreads();
    }
    float denom = __fadd_rn((float)cr[0], EPS_F);

    double h = 0.0;
    #pragma unroll
    for (int q = 0; q < 4; q++) {
        float p = __fdiv_rn((float)g_counts[tid * 4 + q], denom);
        h += (double)__fmul_rn(p, __logf(__fadd_rn(p, EPS_F)));
    }
    hr[tid] = h;
    __syncthreads();
    for (int st = 128; st > 0; st >>= 1) {
        if (tid < st) hr[tid] += hr[tid + st];
        __syncthreads();
    }

    if (tid == 0) {
        float L = (float)(dr[0] / (double)Z_ELEMS);
        out[Z_ELEMS + 0] = L;                                 // commitment
        out[Z_ELEMS + 1] = L;                                 // codebook
        out[Z_ELEMS + 2] = __fadd_rn(L, __fmul_rn(BETA, L));  // cluster
        out[Z_ELEMS + 3] = __expf(-(float)hr[0]);             // perplexity
    }
}

// ---------------------------------------------------------------------------
extern "C" void kernel_launch(void* const* d_in, const int* in_sizes, int n_in,
                              void* d_out, int out_size) {
    const float* z  = (const float*)d_in[0];   // [65536, 256]
    const float* cb = (const float*)d_in[1];   // [1024, 256]
    float* out = (float*)d_out;

    cudaFuncSetAttribute(vq_mma, cudaFuncAttributeMaxDynamicSharedMemorySize,
                         P1_SMEM_BYTES);

    vq_prep_cb<<<KCODES / 32, 256>>>(cb);
    vq_prep_z<<<TOKENS / 32, 256>>>(z);
    vq_mma<<<NBLK_MMA, 256, P1_SMEM_BYTES>>>();
    vq_rerank<<<NBLK_RR, 256>>>(z, cb, out);
    vq_finalize<<<1, 256>>>(out);
}

// round 15
// speedup vs baseline: 4.9448x; 4.9448x over previous
#include <cuda_runtime.h>
#include <cuda_bf16.h>

// Problem constants
#define TOKENS   65536          // 16*64*64
#define DDIM     256
#define KCODES   1024
#define Z_ELEMS  (TOKENS * DDIM)   // 16777216
#define BETA     0.25f
#define EPS_F    1e-5f

// Certified window on s = e2 - 2*ze: E = bf16 mma error <= 2.4e-3; W > 2E.
// Selection thresholds use the RUNNING min (>= final min) -> superset of the
// certified window; expected |candidates| ~ 5-10 (s sigma ~0.018, W=0.55σ),
// so CAND_CAP=64 makes overflow (certified full-scan fallback) negligible.
#define W_WINDOW 0.01f
#define CAND_CAP 64

#define NBLK_MMA  (TOKENS / 64)        // 1024  (64 tokens per CTA)
#define NBLK_RR   (TOKENS / 8)         // 8192  (8 tokens per CTA)

// Phase-1 smem: z bf16 [64][264] | cb stages 2x[256][40] bf16 | e2[1024]
//              | smin[64] scnt[64] scand[64][64]
#define P1_ZB_ELEMS   (64 * 264)                   // 16896 bf16
#define P1_CB_ELEMS   (256 * 40)                   // per stage
#define P1_SMEM_BYTES (P1_ZB_ELEMS * 2 + 2 * P1_CB_ELEMS * 2 + 1024 * 4 \
                       + (64 + 64 + 64 * CAND_CAP) * 4)          // 95744

// Output layout: [0..Z) z_q_st | [Z+0..3] scalars | [Z+4..) indices as float

// Device scratch (static: no allocations allowed)
__device__ int            g_counts[KCODES];
__device__ double         g_partial[NBLK_RR];
__device__ float          g_e2[KCODES];
__device__ float          g_z2[TOKENS];
__device__ __nv_bfloat16  g_cb_bf16[KCODES * DDIM];
__device__ __nv_bfloat16  g_z_bf16[TOKENS * DDIM];
__device__ int            g_ccnt[TOKENS];
__device__ int            g_cand[(size_t)TOKENS * CAND_CAP];

// order-preserving float <-> uint key (ascending)
__device__ __forceinline__ unsigned okey(float v) {
    unsigned b = __float_as_uint(v);
    return b ^ (unsigned)(((int)b >> 31) | 0x80000000);
}
__device__ __forceinline__ float odec(unsigned k) {
    unsigned b = (k & 0x80000000u) ? (k ^ 0x80000000u) : ~k;
    return __uint_as_float(b);
}

// ---------------------------------------------------------------------------
// prep codebook: exact e2 (reference order) + bf16 copy + zero histogram.
// ---------------------------------------------------------------------------
__global__ void __launch_bounds__(256) vq_prep_cb(const float* __restrict__ cb) {
    __shared__ float ct[32 * 260];
    const int tid = threadIdx.x;
    const int k0  = blockIdx.x * 32;
    if (blockIdx.x < 4) g_counts[blockIdx.x * 256 + tid] = 0;
    const float* cbb = cb + (size_t)k0 * DDIM;
    #pragma unroll
    for (int p = 0; p < 32; p++) {
        int e = tid + p * 256;            // 0..8191
        float v = cbb[e];
        ct[(e >> 8) * 260 + (e & 255)] = v;
        g_cb_bf16[(size_t)k0 * DDIM + e] = __float2bfloat16_rn(v);
    }
    __syncthreads();
    if (tid < 32) {
        const float* row = &ct[tid * 260];
        float s = 0.0f;
        #pragma unroll 8
        for (int d = 0; d < DDIM; d++)
            s = __fadd_rn(s, __fmul_rn(row[d], row[d]));
        g_e2[k0 + tid] = s;
    }
}

// ---------------------------------------------------------------------------
// prep z: exact z2 (reference order via padded transpose) + bf16 copy.
// ---------------------------------------------------------------------------
__global__ void __launch_bounds__(256) vq_prep_z(const float* __restrict__ z) {
    __shared__ float zt[32 * 257];
    const int tid  = threadIdx.x;
    const int tok0 = blockIdx.x * 32;
    const float* zb = z + (size_t)tok0 * DDIM;
    #pragma unroll
    for (int p = 0; p < 32; p++) {
        int e = tid + p * 256;
        float v = zb[e];
        zt[(e >> 8) * 257 + (e & 255)] = v;
        g_z_bf16[(size_t)tok0 * DDIM + e] = __float2bfloat16_rn(v);
    }
    __syncthreads();
    if (tid < 32) {
        const float* row = &zt[tid * 257];
        float s = 0.0f;
        #pragma unroll 8
        for (int d = 0; d < DDIM; d++)
            s = __fadd_rn(s, __fmul_rn(row[d], row[d]));
        g_z2[tok0 + tid] = s;
    }
}

// ---------------------------------------------------------------------------
// Phase 1: bf16 mma + FUSED candidate selection (no s matrix materialized).
// CTA = 64 tokens x 1024 codes. 8 warps: mw = w&3 token rows; nh = w>>2 half.
// ---------------------------------------------------------------------------
__global__ void __launch_bounds__(256, 2) vq_mma() {
    extern __shared__ char smem[];
    __nv_bfloat16* zbs = reinterpret_cast<__nv_bfloat16*>(smem);       // [64][264]
    __nv_bfloat16* cbs = zbs + P1_ZB_ELEMS;                            // [2][256][40]
    float*    e2s  = reinterpret_cast<float*>(cbs + 2 * P1_CB_ELEMS);  // [1024]
    unsigned* smin = reinterpret_cast<unsigned*>(e2s + 1024);          // [64]
    int*      scnt = reinterpret_cast<int*>(smin + 64);                // [64]
    int*      scand = scnt + 64;                                       // [64][64]

    const int tid  = threadIdx.x;
    const int lane = tid & 31;
    const int w    = tid >> 5;
    const int mw   = w & 3;
    const int nh   = w >> 2;
    const int tok0 = blockIdx.x * 64;
    const int gid  = lane >> 2;     // groupID
    const int tg   = lane & 3;      // thread-in-group

    // Load z bf16 tile: 2048 x 16B, rows padded to 264.
    {
        const uint4* zg = reinterpret_cast<const uint4*>(g_z_bf16 + (size_t)tok0 * DDIM);
        #pragma unroll
        for (int p = 0; p < 8; p++) {
            int idx = tid + p * 256;          // 0..2047
            int r   = idx >> 5;               // 0..63
            int c8  = idx & 31;
            *reinterpret_cast<uint4*>(zbs + r * 264 + c8 * 8) = zg[idx];
        }
    }
    #pragma unroll
    for (int p = 0; p < 4; p++) e2s[tid + p * 256] = g_e2[tid + p * 256];
    if (tid < 64) { smin[tid] = 0xFFFFFFFFu; scnt[tid] = 0; }

    // stage SI (0..31): chunk = SI>>3, d-stage = SI&7 (32 d per stage)
    #define SL(SI, BUF)                                                          \
    do {                                                                         \
        int c_  = (SI) >> 3;                                                     \
        int st_ = (SI) & 7;                                                      \
        _Pragma("unroll")                                                        \
        for (int q = 0; q < 4; q++) {                                            \
            int idx_ = tid + q * 256;          /* 0..1023 */                     \
            int r_   = idx_ >> 2;              /* 0..255  */                     \
            int sg_  = idx_ & 3;                                                 \
            int g_   = c_ * 128 + (r_ & 127) + (r_ >> 7) * 512;                  \
            const __nv_bfloat16* src_ =                                          \
                g_cb_bf16 + (size_t)g_ * DDIM + st_ * 32 + sg_ * 8;              \
            unsigned dst_ = (unsigned)__cvta_generic_to_shared(                  \
                cbs + (BUF) * P1_CB_ELEMS + r_ * 40 + sg_ * 8);                  \
            asm volatile("cp.async.cg.shared.global [%0], [%1], 16;\n"           \
                         :: "r"(dst_), "l"(src_));                               \
        }                                                                        \
        asm volatile("cp.async.commit_group;\n" ::: "memory");                   \
    } while (0)

    SL(0, 0);
    float acc[16][4];
    int buf = 0;

    for (int c = 0; c < 4; c++) {
        #pragma unroll
        for (int nt = 0; nt < 16; nt++)
            #pragma unroll
            for (int e = 0; e < 4; e++) acc[nt][e] = 0.0f;

        for (int st = 0; st < 8; st++) {
            int sg = c * 8 + st;
            asm volatile("cp.async.wait_group 0;\n" ::: "memory");
            __syncthreads();
            if (sg + 1 < 32) SL(sg + 1, buf ^ 1);

            const __nv_bfloat16* zb =
                zbs + (mw * 16 + gid) * 264 + st * 32 + tg * 2;
            const __nv_bfloat16* cbb =
                cbs + buf * P1_CB_ELEMS + (nh * 128 + gid) * 40 + tg * 2;

            #pragma unroll
            for (int k16 = 0; k16 < 2; k16++) {
                unsigned a0 = *reinterpret_cast<const unsigned*>(zb + k16 * 16);
                unsigned a1 = *reinterpret_cast<const unsigned*>(zb + k16 * 16 + 8 * 264);
                unsigned a2 = *reinterpret_cast<const unsigned*>(zb + k16 * 16 + 8);
                unsigned a3 = *reinterpret_cast<const unsigned*>(zb + k16 * 16 + 8 * 264 + 8);
                #pragma unroll
                for (int nt = 0; nt < 16; nt++) {
                    unsigned b0 = *reinterpret_cast<const unsigned*>(
                        cbb + nt * 320 + k16 * 16);
                    unsigned b1 = *reinterpret_cast<const unsigned*>(
                        cbb + nt * 320 + k16 * 16 + 8);
                    asm volatile(
                        "mma.sync.aligned.m16n8k16.row.col.f32.bf16.bf16.f32 "
                        "{%0,%1,%2,%3}, {%4,%5,%6,%7}, {%8,%9}, {%0,%1,%2,%3};"
                        : "+f"(acc[nt][0]), "+f"(acc[nt][1]),
                          "+f"(acc[nt][2]), "+f"(acc[nt][3])
                        : "r"(a0), "r"(a1), "r"(a2), "r"(a3), "r"(b0), "r"(b1));
                }
            }
            buf ^= 1;
        }

        // ---- fused epilogue: running min + candidate selection ----
        const int t0 = mw * 16 + gid;
        const int kb = nh * 512 + c * 128 + tg * 2;
        float m0 = 3.4e38f, m1 = 3.4e38f;
        #pragma unroll
        for (int nt = 0; nt < 16; nt++) {
            float e20 = e2s[kb + nt * 8], e21 = e2s[kb + nt * 8 + 1];
            m0 = fminf(m0, fminf(e20 - 2.0f * acc[nt][0],
                                 e21 - 2.0f * acc[nt][1]));
            m1 = fminf(m1, fminf(e20 - 2.0f * acc[nt][2],
                                 e21 - 2.0f * acc[nt][3]));
        }
        atomicMin(&smin[t0], okey(m0));
        atomicMin(&smin[t0 + 8], okey(m1));
        __syncthreads();
        {
            float thr0 = odec(smin[t0]) + W_WINDOW;
            float thr1 = odec(smin[t0 + 8]) + W_WINDOW;
            #pragma unroll
            for (int nt = 0; nt < 16; nt++) {
                int kg = kb + nt * 8;
                float e20 = e2s[kg], e21 = e2s[kg + 1];
                float s00 = e20 - 2.0f * acc[nt][0];
                float s01 = e21 - 2.0f * acc[nt][1];
                float s10 = e20 - 2.0f * acc[nt][2];
                float s11 = e21 - 2.0f * acc[nt][3];
                if (s00 <= thr0) { int p = atomicAdd(&scnt[t0], 1);
                    if (p < CAND_CAP) scand[t0 * CAND_CAP + p] = kg; }
                if (s01 <= thr0) { int p = atomicAdd(&scnt[t0], 1);
                    if (p < CAND_CAP) scand[t0 * CAND_CAP + p] = kg + 1; }
                if (s10 <= thr1) { int p = atomicAdd(&scnt[t0 + 8], 1);
                    if (p < CAND_CAP) scand[(t0 + 8) * CAND_CAP + p] = kg; }
                if (s11 <= thr1) { int p = atomicAdd(&scnt[t0 + 8], 1);
                    if (p < CAND_CAP) scand[(t0 + 8) * CAND_CAP + p] = kg + 1; }
            }
        }
    }
    #undef SL

    // write candidates out (64 tokens x 64 slots = 4096 ints)
    __syncthreads();
    if (tid < 64) g_ccnt[tok0 + tid] = scnt[tid];
    #pragma unroll
    for (int p = 0; p < 16; p++) {
        int i = tid + p * 256;            // 0..4095
        g_cand[(size_t)(tok0 + (i >> 6)) * CAND_CAP + (i & 63)] = scand[i];
    }
}

// ---------------------------------------------------------------------------
// Phase 2: per token (1 warp): exact re-rank of candidates (warp-cooperative
// split-d dot + shfl butterfly), then fused gather + z_q_st + loss + hist.
// ---------------------------------------------------------------------------
__global__ void __launch_bounds__(256)
vq_rerank(const float* __restrict__ z, const float* __restrict__ cb,
          float* __restrict__ out) {
    __shared__ float  zsr[8 * DDIM];          // 8 token rows fp32
    __shared__ int    sfin[8];
    __shared__ double dred[256];

    const int tid  = threadIdx.x;
    const int lane = tid & 31;
    const int w    = tid >> 5;
    const int tok0 = blockIdx.x * 8;
    const int t    = tok0 + w;

    // stage z rows (512 float4)
    {
        const float4* zg = reinterpret_cast<const float4*>(z) + (size_t)tok0 * (DDIM / 4);
        #pragma unroll
        for (int p = 0; p < 2; p++) {
            int idx = tid + p * 256;
            reinterpret_cast<float4*>(zsr)[idx] = zg[idx];
        }
    }
    __syncthreads();

    const int cnt = g_ccnt[t];
    float bd = 3.4e38f;
    int   bk = 0;
    const float* zr  = zsr + w * DDIM;
    const float  z2t = g_z2[t];
    const float4* zr4 = reinterpret_cast<const float4*>(zr) + lane * 2;
    float4 zv0 = zr4[0], zv1 = zr4[1];

    #define EXACT_STEP(K)                                                        \
    do {                                                                         \
        int k_ = (K);                                                            \
        const float4* er_ = reinterpret_cast<const float4*>(                     \
            cb + (size_t)k_ * DDIM) + lane * 2;                                  \
        float4 e0_ = er_[0], e1_ = er_[1];                                       \
        float s_ = 0.0f;                                                         \
        s_ = __fmaf_rn(zv0.x, e0_.x, s_);                                        \
        s_ = __fmaf_rn(zv0.y, e0_.y, s_);                                        \
        s_ = __fmaf_rn(zv0.z, e0_.z, s_);                                        \
        s_ = __fmaf_rn(zv0.w, e0_.w, s_);                                        \
        s_ = __fmaf_rn(zv1.x, e1_.x, s_);                                        \
        s_ = __fmaf_rn(zv1.y, e1_.y, s_);                                        \
        s_ = __fmaf_rn(zv1.z, e1_.z, s_);                                        \
        s_ = __fmaf_rn(zv1.w, e1_.w, s_);                                        \
        _Pragma("unroll")                                                        \
        for (int off_ = 16; off_ > 0; off_ >>= 1)                                \
            s_ = __fadd_rn(s_, __shfl_xor_sync(0xFFFFFFFFu, s_, off_));          \
        float dist_ = __fsub_rn(__fadd_rn(z2t, g_e2[k_]),                        \
                                __fmul_rn(2.0f, s_));                            \
        if (dist_ < bd || (dist_ == bd && k_ < bk)) { bd = dist_; bk = k_; }     \
    } while (0)

    if (cnt <= CAND_CAP) {
        const int* cp = &g_cand[(size_t)t * CAND_CAP];
        for (int cc = 0; cc < cnt; cc++) EXACT_STEP(cp[cc]);
    } else {
        for (int k = 0; k < KCODES; k++) EXACT_STEP(k);   // certified fallback
    }
    #undef EXACT_STEP

    if (lane == 0) {
        sfin[w] = bk;
        out[Z_ELEMS + 4 + t] = (float)bk;
        atomicAdd(&g_counts[bk], 1);
    }
    __syncthreads();

    // fused gather + z_q_st + loss partial
    double sacc = 0.0;
    const float4* cb4 = reinterpret_cast<const float4*>(cb);
    float4*       o4  = reinterpret_cast<float4*>(out);
    #pragma unroll
    for (int p = 0; p < 2; p++) {
        int e4 = tid + p * 256;           // 0..511
        int tl = e4 >> 6;
        int d4 = e4 & 63;
        int idx = sfin[tl];
        float4 zq = cb4[(size_t)idx * (DDIM / 4) + d4];
        float4 zz = reinterpret_cast<const float4*>(zsr)[e4];
        float4 o;
        o.x = __fadd_rn(zz.x, __fsub_rn(zq.x, zz.x));
        o.y = __fadd_rn(zz.y, __fsub_rn(zq.y, zz.y));
        o.z = __fadd_rn(zz.z, __fsub_rn(zq.z, zz.z));
        o.w = __fadd_rn(zz.w, __fsub_rn(zq.w, zz.w));
        o4[(size_t)tok0 * (DDIM / 4) + e4] = o;
        float dx = __fsub_rn(zz.x, zq.x);
        float dy = __fsub_rn(zz.y, zq.y);
        float dz = __fsub_rn(zz.z, zq.z);
        float dw = __fsub_rn(zz.w, zq.w);
        sacc += (double)__fmul_rn(dx, dx);
        sacc += (double)__fmul_rn(dy, dy);
        sacc += (double)__fmul_rn(dz, dz);
        sacc += (double)__fmul_rn(dw, dw);
    }
    dred[tid] = sacc;
    __syncthreads();
    for (int stride = 128; stride > 0; stride >>= 1) {
        if (tid < stride) dred[tid] += dred[tid + stride];
        __syncthreads();
    }
    if (tid == 0) g_partial[blockIdx.x] = dred[0];
}

// ---------------------------------------------------------------------------
// finalize (parallel, deterministic fixed-tree reductions in double).
// ---------------------------------------------------------------------------
__global__ void __launch_bounds__(256) vq_finalize(float* __restrict__ out) {
    __shared__ double dr[256];
    __shared__ double hr[256];
    __shared__ int    cr[256];
    const int tid = threadIdx.x;

    double s = 0.0;
    for (int q = 0; q < NBLK_RR / 256; q++) s += g_partial[tid * (NBLK_RR / 256) + q];
    dr[tid] = s;

    int c = 0;
    #pragma unroll
    for (int q = 0; q < 4; q++) c += g_counts[tid * 4 + q];
    cr[tid] = c;
    __syncthreads();
    for (int st = 128; st > 0; st >>= 1) {
        if (tid < st) { dr[tid] += dr[tid + st]; cr[tid] += cr[tid + st]; }
        __syncthreads();
    }
    float denom = __fadd_rn((float)cr[0], EPS_F);

    double h = 0.0;
    #pragma unroll
    for (int q = 0; q < 4; q++) {
        float p = __fdiv_rn((float)g_counts[tid * 4 + q], denom);
        h += (double)__fmul_rn(p, __logf(__fadd_rn(p, EPS_F)));
    }
    hr[tid] = h;
    __syncthreads();
    for (int st = 128; st > 0; st >>= 1) {
        if (tid < st) hr[tid] += hr[tid + st];
        __syncthreads();
    }

    if (tid == 0) {
        float L = (float)(dr[0] / (double)Z_ELEMS);
        out[Z_ELEMS + 0] = L;                                 // commitment
        out[Z_ELEMS + 1] = L;                                 // codebook
        out[Z_ELEMS + 2] = __fadd_rn(L, __fmul_rn(BETA, L));  // cluster
        out[Z_ELEMS + 3] = __expf(-(float)hr[0]);             // perplexity
    }
}

// ---------------------------------------------------------------------------
extern "C" void kernel_launch(void* const* d_in, const int* in_sizes, int n_in,
                              void* d_out, int out_size) {
    const float* z  = (const float*)d_in[0];   // [65536, 256]
    const float* cb = (const float*)d_in[1];   // [1024, 256]
    float* out = (float*)d_out;

    cudaFuncSetAttribute(vq_mma, cudaFuncAttributeMaxDynamicSharedMemorySize,
                         P1_SMEM_BYTES);

    vq_prep_cb<<<KCODES / 32, 256>>>(cb);
    vq_prep_z<<<TOKENS / 32, 256>>>(z);
    vq_mma<<<NBLK_MMA, 256, P1_SMEM_BYTES>>>();
    vq_rerank<<<NBLK_RR, 256>>>(z, cb, out);
    vq_finalize<<<1, 256>>>(out);
}